// round 8
// baseline (speedup 1.0000x reference)
#include <cuda_runtime.h>
#include <cuda_bf16.h>
#include <math.h>

#define TILE_M 128
#define THREADS 128
#define SAB 136   // bf16 elements per smem row (272B) -> conflict-free LDSM

#define MAX_N 100096
#define W1_OFF 0
#define W2_OFF (256*128)
#define W3_OFF (256*128 + 128*128)
#define W_TOTAL (256*128 + 2*128*128)

// smem: sA[128*SAB bf16] | sB[128*SAB bf16] | sIdx[256] | sW4[128] | sB3[128] | sPart[256]
#define SMEM_BYTES (2*128*SAB*2 + 256*4 + 128*4 + 128*4 + 256*4)

__device__ __nv_bfloat16 g_xbf[(size_t)MAX_N * 128];
__device__ __nv_bfloat16 g_wbf[W_TOTAL];

// ---------------- prep: fp32 -> bf16 ----------------
__global__ void cvt_x_kernel(const float* __restrict__ x, int n4) {
    int i = blockIdx.x * blockDim.x + threadIdx.x;   // over N*32 float4s
    if (i >= n4) return;
    float4 v = ((const float4*)x)[i];
    __nv_bfloat162 p0 = __floats2bfloat162_rn(v.x, v.y);
    __nv_bfloat162 p1 = __floats2bfloat162_rn(v.z, v.w);
    uint2 o; o.x = *(unsigned*)&p0; o.y = *(unsigned*)&p1;
    ((uint2*)g_xbf)[i] = o;
}
__global__ void cvt_w_kernel(const float* __restrict__ W1,
                             const float* __restrict__ W2,
                             const float* __restrict__ W3) {
    int i = blockIdx.x * blockDim.x + threadIdx.x;   // over W_TOTAL/4 float4s
    if (i >= W_TOTAL / 4) return;
    int e = i * 4;
    const float* src = (e < W2_OFF) ? (W1 + e)
                     : (e < W3_OFF) ? (W2 + (e - W2_OFF))
                                    : (W3 + (e - W3_OFF));
    float4 v = *(const float4*)src;
    __nv_bfloat162 p0 = __floats2bfloat162_rn(v.x, v.y);
    __nv_bfloat162 p1 = __floats2bfloat162_rn(v.z, v.w);
    uint2 o; o.x = *(unsigned*)&p0; o.y = *(unsigned*)&p1;
    ((uint2*)g_wbf)[i] = o;
}

// ---------------- mma helpers ----------------
__device__ __forceinline__ void ldsm_x4(unsigned* r, unsigned addr) {
    asm volatile("ldmatrix.sync.aligned.m8n8.x4.shared.b16 {%0,%1,%2,%3}, [%4];"
        : "=r"(r[0]), "=r"(r[1]), "=r"(r[2]), "=r"(r[3]) : "r"(addr));
}
__device__ __forceinline__ void ldsm_x4_t(unsigned* r, unsigned addr) {
    asm volatile("ldmatrix.sync.aligned.m8n8.x4.trans.shared.b16 {%0,%1,%2,%3}, [%4];"
        : "=r"(r[0]), "=r"(r[1]), "=r"(r[2]), "=r"(r[3]) : "r"(addr));
}
__device__ __forceinline__ void mma_bf16(float* c, const unsigned* a, const unsigned* b) {
    asm volatile(
        "mma.sync.aligned.m16n8k16.row.col.f32.bf16.bf16.f32 "
        "{%0,%1,%2,%3},{%4,%5,%6,%7},{%8,%9},{%0,%1,%2,%3};"
        : "+f"(c[0]), "+f"(c[1]), "+f"(c[2]), "+f"(c[3])
        : "r"(a[0]), "r"(a[1]), "r"(a[2]), "r"(a[3]), "r"(b[0]), "r"(b[1]));
}

__global__ void __launch_bounds__(THREADS, 3)
edgepred_bf16_kernel(
    const int* __restrict__ ei,
    const float* __restrict__ b1, const float* __restrict__ b2,
    const float* __restrict__ b3,
    const float* __restrict__ W4, const float* __restrict__ b4,
    float* __restrict__ out, int E, int N)
{
    extern __shared__ char smem_raw[];
    __nv_bfloat16* sA = (__nv_bfloat16*)smem_raw;            // 128 x SAB
    __nv_bfloat16* sB = sA + 128 * SAB;                      // 128 x SAB
    int*   sIdx  = (int*)(sB + 128 * SAB);                   // 256
    float* sW4   = (float*)(sIdx + 256);                     // 128
    float* sB3   = sW4 + 128;                                // 128
    float* sPart = sB3 + 128;                                // 2 x 128

    const int tid    = threadIdx.x;
    const int lane   = tid & 31;
    const int wid    = tid >> 5;                 // 0..3
    const int warp_m = wid >> 1;                 // 0..1 -> rows [warp_m*64, +64)
    const int warp_n = wid & 1;                  // 0..1 -> cols [warp_n*64, +64)
    const int qid    = lane >> 2;
    const int tig    = lane & 3;
    const long long tile0 = (long long)blockIdx.x * TILE_M;

    const unsigned sA_u = (unsigned)__cvta_generic_to_shared(sA);
    const unsigned sB_u = (unsigned)__cvta_generic_to_shared(sB);

    // ---- edge indices (src / dst), clamped; small params ----
    #pragma unroll
    for (int h = 0; h < 2; ++h) {
        long long e = tile0 + tid;
        int idx = 0;
        if (e < E) idx = ei[(long long)h * E + e];
        if (idx < 0)  idx = 0;
        if (idx >= N) idx = N - 1;
        sIdx[h * 128 + tid] = idx;
    }
    sW4[tid] = W4[tid];
    sB3[tid] = b3[tid];
    __syncthreads();

    // ---- coalesced bf16 row loaders: one warp per 256B row, 32 rows/warp ----
    auto copy_row = [&](const __nv_bfloat16* srcRow, __nv_bfloat16* dstRow) {
        uint2 v = ((const uint2*)srcRow)[lane];          // 8B/lane = full 256B row
        *(uint2*)(dstRow + lane * 4) = v;                // STS.64 conflict-free
    };
    auto load_act = [&](const int* idxs) {
        #pragma unroll
        for (int r = 0; r < 32; ++r) {
            int row = wid + r * 4;
            int node = idxs[row];
            copy_row(g_xbf + (size_t)node * 128, sA + row * SAB);
        }
    };
    auto load_w = [&](const __nv_bfloat16* W) {
        #pragma unroll
        for (int r = 0; r < 32; ++r) {
            int row = wid + r * 4;
            copy_row(W + row * 128, sB + row * SAB);
        }
    };

    // ---- per-lane LDSM base addresses ----
    const int sub = lane >> 3;
    const int r8  = lane & 7;
    const unsigned aBase = sA_u + (((sub & 1) * 8 + r8) * SAB + (sub >> 1) * 8) * 2;
    const unsigned bBase = sB_u + (((sub & 1) * 8 + r8) * SAB + warp_n * 64 + (sub >> 1) * 8) * 2;

    float acc[4][8][4];   // 64x64 warp tile: mt x nt x 4
    auto zero_acc = [&]() {
        #pragma unroll
        for (int mt = 0; mt < 4; ++mt)
            #pragma unroll
            for (int nt = 0; nt < 8; ++nt)
                #pragma unroll
                for (int i = 0; i < 4; ++i) acc[mt][nt][i] = 0.f;
    };

    // 128x128x128 GEMM pass (per warp: 64x64): sA @ sB -> acc
    auto run_mma = [&]() {
        #pragma unroll
        for (int kt = 0; kt < 8; ++kt) {
            unsigned a[4][4], b[4][4];
            #pragma unroll
            for (int mt = 0; mt < 4; ++mt)
                ldsm_x4(a[mt], aBase + (unsigned)((warp_m * 64 + mt * 16) * SAB + kt * 16) * 2);
            #pragma unroll
            for (int ntp = 0; ntp < 4; ++ntp)
                ldsm_x4_t(b[ntp], bBase + (unsigned)(kt * 16 * SAB + ntp * 16) * 2);
            #pragma unroll
            for (int mt = 0; mt < 4; ++mt)
                #pragma unroll
                for (int nt = 0; nt < 8; ++nt)
                    mma_bf16(acc[mt][nt], a[mt], &b[nt >> 1][(nt & 1) * 2]);
        }
    };

    // bias + relu -> bf16 back into sA
    auto epilogue = [&](const float* __restrict__ bias) {
        #pragma unroll
        for (int mt = 0; mt < 4; ++mt) {
            int row = warp_m * 64 + mt * 16 + qid;
            #pragma unroll
            for (int nt = 0; nt < 8; ++nt) {
                int col = warp_n * 64 + nt * 8 + 2 * tig;
                float bb0 = __ldg(&bias[col]);
                float bb1 = __ldg(&bias[col + 1]);
                float v0 = fmaxf(acc[mt][nt][0] + bb0, 0.f);
                float v1 = fmaxf(acc[mt][nt][1] + bb1, 0.f);
                float v2 = fmaxf(acc[mt][nt][2] + bb0, 0.f);
                float v3 = fmaxf(acc[mt][nt][3] + bb1, 0.f);
                *(__nv_bfloat162*)(sA + row * SAB + col)       = __floats2bfloat162_rn(v0, v1);
                *(__nv_bfloat162*)(sA + (row + 8) * SAB + col) = __floats2bfloat162_rn(v2, v3);
            }
        }
    };

    // ======== Layer 1, pass A: x_i @ W1[0:128] ========
    load_act(sIdx);
    load_w(g_wbf + W1_OFF);
    __syncthreads();
    zero_acc();
    run_mma();
    __syncthreads();

    // ======== Layer 1, pass B: + x_j @ W1[128:256] ========
    load_act(sIdx + 128);
    load_w(g_wbf + W1_OFF + 128 * 128);
    __syncthreads();
    run_mma();
    __syncthreads();
    load_w(g_wbf + W2_OFF);   // LDGs first -> overlap with epilogue math
    epilogue(b1);
    __syncthreads();

    // ======== Layer 2 ========
    zero_acc();
    run_mma();
    __syncthreads();
    load_w(g_wbf + W3_OFF);
    epilogue(b2);
    __syncthreads();

    // ======== Layer 3 ========
    zero_acc();
    run_mma();

    // ======== Layer 4 from registers: relu(acc + b3) . W4, quad-reduce ========
    {
        #pragma unroll
        for (int mt = 0; mt < 4; ++mt) {
            float z0 = 0.f, z1 = 0.f;       // rows (base+qid) and (base+qid+8)
            #pragma unroll
            for (int nt = 0; nt < 8; ++nt) {
                int col = warp_n * 64 + nt * 8 + 2 * tig;
                float bb0 = sB3[col], bb1 = sB3[col + 1];
                float w0  = sW4[col], w1  = sW4[col + 1];
                z0 += fmaxf(acc[mt][nt][0] + bb0, 0.f) * w0
                    + fmaxf(acc[mt][nt][1] + bb1, 0.f) * w1;
                z1 += fmaxf(acc[mt][nt][2] + bb0, 0.f) * w0
                    + fmaxf(acc[mt][nt][3] + bb1, 0.f) * w1;
            }
            // reduce across the 4-lane quad (same qid, tig 0..3)
            z0 += __shfl_xor_sync(0xFFFFFFFF, z0, 1);
            z0 += __shfl_xor_sync(0xFFFFFFFF, z0, 2);
            z1 += __shfl_xor_sync(0xFFFFFFFF, z1, 1);
            z1 += __shfl_xor_sync(0xFFFFFFFF, z1, 2);
            if (tig == 0) {
                int row = warp_m * 64 + mt * 16 + qid;
                sPart[warp_n * 128 + row]     = z0;
                sPart[warp_n * 128 + row + 8] = z1;
            }
        }
    }
    __syncthreads();
    {
        long long e = tile0 + tid;
        if (e < E) {
            float z = sPart[tid] + sPart[128 + tid] + __ldg(b4);
            out[e] = 1.f / (1.f + expf(-z));
        }
    }
}

extern "C" void kernel_launch(void* const* d_in, const int* in_sizes, int n_in,
                              void* d_out, int out_size)
{
    const float* x  = (const float*)d_in[0];
    const int*   ei = (const int*)d_in[1];
    const float* W1 = (const float*)d_in[2];
    const float* b1 = (const float*)d_in[3];
    const float* W2 = (const float*)d_in[4];
    const float* b2 = (const float*)d_in[5];
    const float* W3 = (const float*)d_in[6];
    const float* b3 = (const float*)d_in[7];
    const float* W4 = (const float*)d_in[8];
    const float* b4 = (const float*)d_in[9];
    float* out = (float*)d_out;

    int E = in_sizes[1] / 2;    // edge_index is (2, E)
    int N = in_sizes[0] / 128;  // x is (N, 128)
    if (N > MAX_N) N = MAX_N;

    // prep: convert x and weights to bf16 scratch
    int n4 = N * 32;
    cvt_x_kernel<<<(n4 + 511) / 512, 512>>>(x, n4);
    cvt_w_kernel<<<(W_TOTAL / 4 + 255) / 256, 256>>>(W1, W2, W3);

    int nTiles = (E + TILE_M - 1) / TILE_M;
    cudaFuncSetAttribute(edgepred_bf16_kernel,
                         cudaFuncAttributeMaxDynamicSharedMemorySize, SMEM_BYTES);
    edgepred_bf16_kernel<<<nTiles, THREADS, SMEM_BYTES>>>(
        ei, b1, b2, b3, W4, b4, out, E, N);
}

// round 9
// speedup vs baseline: 1.2812x; 1.2812x over previous
#include <cuda_runtime.h>
#include <cuda_bf16.h>
#include <math.h>

#define TILE_M 128
#define THREADS 256
#define SAB 136                 // bf16 per smem row (272B) -> conflict-free LDSM
#define ROWB (SAB * 2)          // 272 bytes per row

#define MAX_N 100096
#define W1_OFF 0
#define W2_OFF (256*128)
#define W3_OFF (256*128 + 128*128)
#define W_TOTAL (256*128 + 2*128*128)

// smem (bytes): sA | sB0 | sB1 | sIdx[256i] | sW4[128f] | sB3[128f] | sPart[512f]
#define TILE_B   (128 * ROWB)   // 34816
#define SA_OFF   0
#define SB0_OFF  TILE_B
#define SB1_OFF  (2 * TILE_B)
#define SIDX_OFF (3 * TILE_B)
#define SW4_OFF  (SIDX_OFF + 1024)
#define SB3_OFF  (SW4_OFF + 512)
#define SPART_OFF (SB3_OFF + 512)
#define SMEM_BYTES (SPART_OFF + 2048)

__device__ __nv_bfloat16 g_xbf[(size_t)MAX_N * 128];
__device__ __nv_bfloat16 g_wbf[W_TOTAL];

// ---------------- prep: fp32 -> bf16 ----------------
__global__ void cvt_x_kernel(const float* __restrict__ x, int n4) {
    int i = blockIdx.x * blockDim.x + threadIdx.x;
    if (i >= n4) return;
    float4 v = ((const float4*)x)[i];
    __nv_bfloat162 p0 = __floats2bfloat162_rn(v.x, v.y);
    __nv_bfloat162 p1 = __floats2bfloat162_rn(v.z, v.w);
    uint2 o; o.x = *(unsigned*)&p0; o.y = *(unsigned*)&p1;
    ((uint2*)g_xbf)[i] = o;
}
__global__ void cvt_w_kernel(const float* __restrict__ W1,
                             const float* __restrict__ W2,
                             const float* __restrict__ W3) {
    int i = blockIdx.x * blockDim.x + threadIdx.x;
    if (i >= W_TOTAL / 4) return;
    int e = i * 4;
    const float* src = (e < W2_OFF) ? (W1 + e)
                     : (e < W3_OFF) ? (W2 + (e - W2_OFF))
                                    : (W3 + (e - W3_OFF));
    float4 v = *(const float4*)src;
    __nv_bfloat162 p0 = __floats2bfloat162_rn(v.x, v.y);
    __nv_bfloat162 p1 = __floats2bfloat162_rn(v.z, v.w);
    uint2 o; o.x = *(unsigned*)&p0; o.y = *(unsigned*)&p1;
    ((uint2*)g_wbf)[i] = o;
}

// ---------------- async copy + mma helpers ----------------
__device__ __forceinline__ void cp16(unsigned dst, const void* src) {
    asm volatile("cp.async.ca.shared.global [%0], [%1], 16;" :: "r"(dst), "l"(src));
}
#define CP_COMMIT() asm volatile("cp.async.commit_group;" ::: "memory")
#define CP_WAIT(n)  asm volatile("cp.async.wait_group %0;" :: "n"(n) : "memory")

__device__ __forceinline__ void ldsm_x4(unsigned* r, unsigned addr) {
    asm volatile("ldmatrix.sync.aligned.m8n8.x4.shared.b16 {%0,%1,%2,%3}, [%4];"
        : "=r"(r[0]), "=r"(r[1]), "=r"(r[2]), "=r"(r[3]) : "r"(addr));
}
__device__ __forceinline__ void ldsm_x4_t(unsigned* r, unsigned addr) {
    asm volatile("ldmatrix.sync.aligned.m8n8.x4.trans.shared.b16 {%0,%1,%2,%3}, [%4];"
        : "=r"(r[0]), "=r"(r[1]), "=r"(r[2]), "=r"(r[3]) : "r"(addr));
}
__device__ __forceinline__ void mma_bf16(float* c, const unsigned* a, const unsigned* b) {
    asm volatile(
        "mma.sync.aligned.m16n8k16.row.col.f32.bf16.bf16.f32 "
        "{%0,%1,%2,%3},{%4,%5,%6,%7},{%8,%9},{%0,%1,%2,%3};"
        : "+f"(c[0]), "+f"(c[1]), "+f"(c[2]), "+f"(c[3])
        : "r"(a[0]), "r"(a[1]), "r"(a[2]), "r"(a[3]), "r"(b[0]), "r"(b[1]));
}

__global__ void __launch_bounds__(THREADS, 2)
edgepred_bf16_kernel(
    const int* __restrict__ ei,
    const float* __restrict__ b1, const float* __restrict__ b2,
    const float* __restrict__ b3,
    const float* __restrict__ W4, const float* __restrict__ b4,
    float* __restrict__ out, int E, int N)
{
    extern __shared__ char smem[];
    __nv_bfloat16* sA = (__nv_bfloat16*)(smem + SA_OFF);
    int*   sIdx  = (int*)(smem + SIDX_OFF);
    float* sW4   = (float*)(smem + SW4_OFF);
    float* sB3   = (float*)(smem + SB3_OFF);
    float* sPart = (float*)(smem + SPART_OFF);   // 4 x 128

    const int tid    = threadIdx.x;
    const int lane   = tid & 31;
    const int wid    = tid >> 5;                 // 0..7
    const int warp_m = wid >> 2;                 // 0..1
    const int warp_n = wid & 3;                  // 0..3
    const int qid    = lane >> 2;
    const int tig    = lane & 3;
    const long long tile0 = (long long)blockIdx.x * TILE_M;

    const unsigned smem_u = (unsigned)__cvta_generic_to_shared(smem);
    const unsigned sA_u   = smem_u + SA_OFF;
    const unsigned sB0_u  = smem_u + SB0_OFF;
    const unsigned sB1_u  = smem_u + SB1_OFF;

    // ---- edge indices + small params ----
    {
        int half = (tid < 128) ? 0 : 1;
        int r = tid & 127;
        long long e = tile0 + r;
        int idx = 0;
        if (e < E) idx = ei[(long long)half * E + e];
        if (idx < 0)  idx = 0;
        if (idx >= N) idx = N - 1;
        sIdx[half * 128 + r] = idx;
    }
    if (tid < 128) { sW4[tid] = W4[tid]; sB3[tid] = b3[tid]; }
    __syncthreads();

    // ---- async loaders: 16 lanes per 256B row, 2 rows per warp-iter ----
    const int halfw = lane >> 4;       // 0/1
    const int l16   = lane & 15;
    auto load_act = [&](const int* idxs) {
        #pragma unroll
        for (int r = 0; r < 8; ++r) {
            int row = wid * 2 + halfw + r * 16;
            int node = idxs[row];
            cp16(sA_u + row * ROWB + l16 * 16,
                 (const char*)(g_xbf + (size_t)node * 128) + l16 * 16);
        }
    };
    auto load_w = [&](const __nv_bfloat16* W, unsigned dst_u) {
        #pragma unroll
        for (int r = 0; r < 8; ++r) {
            int row = wid * 2 + halfw + r * 16;
            cp16(dst_u + row * ROWB + l16 * 16,
                 (const char*)(W + row * 128) + l16 * 16);
        }
    };

    // ---- LDSM bases ----
    const int sub = lane >> 3;
    const int r8  = lane & 7;
    const unsigned aBase  = sA_u + (((sub & 1) * 8 + r8) * SAB + (sub >> 1) * 8) * 2;
    const unsigned bLocal = (unsigned)((((sub & 1) * 8 + r8) * SAB + warp_n * 32 + (sub >> 1) * 8) * 2);

    float acc[4][4][4];
    auto zero_acc = [&]() {
        #pragma unroll
        for (int mt = 0; mt < 4; ++mt)
            #pragma unroll
            for (int nt = 0; nt < 4; ++nt)
                #pragma unroll
                for (int i = 0; i < 4; ++i) acc[mt][nt][i] = 0.f;
    };

    auto run_mma = [&](unsigned sBu) {
        const unsigned bBase = sBu + bLocal;
        #pragma unroll
        for (int kt = 0; kt < 8; ++kt) {
            unsigned a[4][4], b[2][4];
            #pragma unroll
            for (int mt = 0; mt < 4; ++mt)
                ldsm_x4(a[mt], aBase + (unsigned)((warp_m * 64 + mt * 16) * SAB + kt * 16) * 2);
            #pragma unroll
            for (int ntp = 0; ntp < 2; ++ntp)
                ldsm_x4_t(b[ntp], bBase + (unsigned)(kt * 16 * SAB + ntp * 16) * 2);
            #pragma unroll
            for (int mt = 0; mt < 4; ++mt)
                #pragma unroll
                for (int nt = 0; nt < 4; ++nt)
                    mma_bf16(acc[mt][nt], a[mt], &b[nt >> 1][(nt & 1) * 2]);
        }
    };

    auto epilogue = [&](const float* __restrict__ bias) {
        #pragma unroll
        for (int mt = 0; mt < 4; ++mt) {
            int row = warp_m * 64 + mt * 16 + qid;
            #pragma unroll
            for (int nt = 0; nt < 4; ++nt) {
                int col = warp_n * 32 + nt * 8 + 2 * tig;
                float bb0 = __ldg(&bias[col]);
                float bb1 = __ldg(&bias[col + 1]);
                float v0 = fmaxf(acc[mt][nt][0] + bb0, 0.f);
                float v1 = fmaxf(acc[mt][nt][1] + bb1, 0.f);
                float v2 = fmaxf(acc[mt][nt][2] + bb0, 0.f);
                float v3 = fmaxf(acc[mt][nt][3] + bb1, 0.f);
                *(__nv_bfloat162*)(sA + row * SAB + col)       = __floats2bfloat162_rn(v0, v1);
                *(__nv_bfloat162*)(sA + (row + 8) * SAB + col) = __floats2bfloat162_rn(v2, v3);
            }
        }
    };

    // ======== pipeline ========
    load_act(sIdx);                      // g0: x_i -> sA, W1a -> sB0
    load_w(g_wbf + W1_OFF, sB0_u);
    CP_COMMIT();
    load_w(g_wbf + W1_OFF + 128 * 128, sB1_u);   // g1: W1b -> sB1
    CP_COMMIT();

    CP_WAIT(1);                          // g0 done (W1b may stream under MMA)
    __syncthreads();
    zero_acc();
    run_mma(sB0_u);                      // L1A
    __syncthreads();                     // sA free

    load_act(sIdx + 128);                // g2: x_j -> sA
    CP_COMMIT();
    load_w(g_wbf + W2_OFF, sB0_u);       // g3: W2 -> sB0 (overlaps L1B)
    CP_COMMIT();

    CP_WAIT(1);                          // g1, g2 done
    __syncthreads();
    run_mma(sB1_u);                      // L1B (accumulate)
    __syncthreads();

    load_w(g_wbf + W3_OFF, sB1_u);       // g4: W3 -> sB1 (overlaps L2)
    CP_COMMIT();
    epilogue(b1);                        // h1 -> sA
    CP_WAIT(1);                          // g3 done
    __syncthreads();
    zero_acc();
    run_mma(sB0_u);                      // L2
    __syncthreads();

    epilogue(b2);                        // h2 -> sA
    CP_WAIT(0);                          // g4 done
    __syncthreads();
    zero_acc();
    run_mma(sB1_u);                      // L3

    // ======== L4 from registers: relu(acc + b3) . W4, quad-reduce ========
    #pragma unroll
    for (int mt = 0; mt < 4; ++mt) {
        float z0 = 0.f, z1 = 0.f;
        #pragma unroll
        for (int nt = 0; nt < 4; ++nt) {
            int col = warp_n * 32 + nt * 8 + 2 * tig;
            float bb0 = sB3[col], bb1 = sB3[col + 1];
            float w0  = sW4[col], w1  = sW4[col + 1];
            z0 += fmaxf(acc[mt][nt][0] + bb0, 0.f) * w0
                + fmaxf(acc[mt][nt][1] + bb1, 0.f) * w1;
            z1 += fmaxf(acc[mt][nt][2] + bb0, 0.f) * w0
                + fmaxf(acc[mt][nt][3] + bb1, 0.f) * w1;
        }
        z0 += __shfl_xor_sync(0xFFFFFFFF, z0, 1);
        z0 += __shfl_xor_sync(0xFFFFFFFF, z0, 2);
        z1 += __shfl_xor_sync(0xFFFFFFFF, z1, 1);
        z1 += __shfl_xor_sync(0xFFFFFFFF, z1, 2);
        if (tig == 0) {
            int row = warp_m * 64 + mt * 16 + qid;
            sPart[warp_n * 128 + row]     = z0;
            sPart[warp_n * 128 + row + 8] = z1;
        }
    }
    __syncthreads();
    if (tid < 128) {
        long long e = tile0 + tid;
        if (e < E) {
            float z = sPart[tid] + sPart[128 + tid] + sPart[256 + tid]
                    + sPart[384 + tid] + __ldg(b4);
            out[e] = 1.f / (1.f + expf(-z));
        }
    }
}

extern "C" void kernel_launch(void* const* d_in, const int* in_sizes, int n_in,
                              void* d_out, int out_size)
{
    const float* x  = (const float*)d_in[0];
    const int*   ei = (const int*)d_in[1];
    const float* W1 = (const float*)d_in[2];
    const float* b1 = (const float*)d_in[3];
    const float* W2 = (const float*)d_in[4];
    const float* b2 = (const float*)d_in[5];
    const float* W3 = (const float*)d_in[6];
    const float* b3 = (const float*)d_in[7];
    const float* W4 = (const float*)d_in[8];
    const float* b4 = (const float*)d_in[9];
    float* out = (float*)d_out;

    int E = in_sizes[1] / 2;
    int N = in_sizes[0] / 128;
    if (N > MAX_N) N = MAX_N;

    int n4 = N * 32;
    cvt_x_kernel<<<(n4 + 511) / 512, 512>>>(x, n4);
    cvt_w_kernel<<<(W_TOTAL / 4 + 255) / 256, 256>>>(W1, W2, W3);

    int nTiles = (E + TILE_M - 1) / TILE_M;
    cudaFuncSetAttribute(edgepred_bf16_kernel,
                         cudaFuncAttributeMaxDynamicSharedMemorySize, SMEM_BYTES);
    edgepred_bf16_kernel<<<nTiles, THREADS, SMEM_BYTES>>>(
        ei, b1, b2, b3, W4, b4, out, E, N);
}

// round 10
// speedup vs baseline: 1.2922x; 1.0086x over previous
#include <cuda_runtime.h>
#include <cuda_bf16.h>
#include <math.h>

#define TILE_M 128
#define THREADS 256
#define SAB 136                 // bf16 per smem row (272B) -> conflict-free LDSM
#define ROWB (SAB * 2)          // 272 bytes per row

#define MAX_N 100096
#define W1_OFF 0
#define W2_OFF (256*128)
#define W3_OFF (256*128 + 128*128)
#define W_TOTAL (256*128 + 2*128*128)

// smem (bytes): sA | sB0 | sB1 | sIdx[256i] | sW4[128f] | sBias[3*128f] | sPart[512f]
#define TILE_B   (128 * ROWB)   // 34816
#define SA_OFF   0
#define SB0_OFF  TILE_B
#define SB1_OFF  (2 * TILE_B)
#define SIDX_OFF (3 * TILE_B)
#define SW4_OFF  (SIDX_OFF + 1024)
#define SBIAS_OFF (SW4_OFF + 512)
#define SPART_OFF (SBIAS_OFF + 1536)
#define SMEM_BYTES (SPART_OFF + 2048)

__device__ __nv_bfloat16 g_xbf[(size_t)MAX_N * 128];
__device__ __nv_bfloat16 g_wbf[W_TOTAL];

// ---------------- prep: fp32 -> bf16, 16B stores ----------------
__global__ void cvt_x_kernel(const float* __restrict__ x, int n8) {
    int i = blockIdx.x * blockDim.x + threadIdx.x;   // over N*16 (8 floats each)
    if (i >= n8) return;
    float4 v0 = ((const float4*)x)[2 * i];
    float4 v1 = ((const float4*)x)[2 * i + 1];
    __nv_bfloat162 p0 = __floats2bfloat162_rn(v0.x, v0.y);
    __nv_bfloat162 p1 = __floats2bfloat162_rn(v0.z, v0.w);
    __nv_bfloat162 p2 = __floats2bfloat162_rn(v1.x, v1.y);
    __nv_bfloat162 p3 = __floats2bfloat162_rn(v1.z, v1.w);
    uint4 o;
    o.x = *(unsigned*)&p0; o.y = *(unsigned*)&p1;
    o.z = *(unsigned*)&p2; o.w = *(unsigned*)&p3;
    ((uint4*)g_xbf)[i] = o;
}
__global__ void cvt_w_kernel(const float* __restrict__ W1,
                             const float* __restrict__ W2,
                             const float* __restrict__ W3) {
    int i = blockIdx.x * blockDim.x + threadIdx.x;   // over W_TOTAL/8
    if (i >= W_TOTAL / 8) return;
    int e = i * 8;
    const float* src = (e < W2_OFF) ? (W1 + e)
                     : (e < W3_OFF) ? (W2 + (e - W2_OFF))
                                    : (W3 + (e - W3_OFF));
    float4 v0 = ((const float4*)src)[0];
    float4 v1 = ((const float4*)src)[1];
    __nv_bfloat162 p0 = __floats2bfloat162_rn(v0.x, v0.y);
    __nv_bfloat162 p1 = __floats2bfloat162_rn(v0.z, v0.w);
    __nv_bfloat162 p2 = __floats2bfloat162_rn(v1.x, v1.y);
    __nv_bfloat162 p3 = __floats2bfloat162_rn(v1.z, v1.w);
    uint4 o;
    o.x = *(unsigned*)&p0; o.y = *(unsigned*)&p1;
    o.z = *(unsigned*)&p2; o.w = *(unsigned*)&p3;
    ((uint4*)g_wbf)[i] = o;
}

// ---------------- async copy + mma helpers ----------------
__device__ __forceinline__ void cp16(unsigned dst, const void* src) {
    asm volatile("cp.async.ca.shared.global [%0], [%1], 16;" :: "r"(dst), "l"(src));
}
#define CP_COMMIT() asm volatile("cp.async.commit_group;" ::: "memory")
#define CP_WAIT(n)  asm volatile("cp.async.wait_group %0;" :: "n"(n) : "memory")
#define HALF_BAR(id) asm volatile("bar.sync %0, 128;" :: "r"(id) : "memory")

__device__ __forceinline__ void ldsm_x4(unsigned* r, unsigned addr) {
    asm volatile("ldmatrix.sync.aligned.m8n8.x4.shared.b16 {%0,%1,%2,%3}, [%4];"
        : "=r"(r[0]), "=r"(r[1]), "=r"(r[2]), "=r"(r[3]) : "r"(addr));
}
__device__ __forceinline__ void ldsm_x4_t(unsigned* r, unsigned addr) {
    asm volatile("ldmatrix.sync.aligned.m8n8.x4.trans.shared.b16 {%0,%1,%2,%3}, [%4];"
        : "=r"(r[0]), "=r"(r[1]), "=r"(r[2]), "=r"(r[3]) : "r"(addr));
}
__device__ __forceinline__ void mma_bf16(float* c, const unsigned* a, const unsigned* b) {
    asm volatile(
        "mma.sync.aligned.m16n8k16.row.col.f32.bf16.bf16.f32 "
        "{%0,%1,%2,%3},{%4,%5,%6,%7},{%8,%9},{%0,%1,%2,%3};"
        : "+f"(c[0]), "+f"(c[1]), "+f"(c[2]), "+f"(c[3])
        : "r"(a[0]), "r"(a[1]), "r"(a[2]), "r"(a[3]), "r"(b[0]), "r"(b[1]));
}

__global__ void __launch_bounds__(THREADS, 2)
edgepred_bf16_kernel(
    const int* __restrict__ ei,
    const float* __restrict__ b1, const float* __restrict__ b2,
    const float* __restrict__ b3,
    const float* __restrict__ W4, const float* __restrict__ b4,
    float* __restrict__ out, int E, int N)
{
    extern __shared__ char smem[];
    __nv_bfloat16* sA = (__nv_bfloat16*)(smem + SA_OFF);
    int*   sIdx  = (int*)(smem + SIDX_OFF);
    float* sW4   = (float*)(smem + SW4_OFF);
    float* sBias = (float*)(smem + SBIAS_OFF);   // b1 | b2 | b3
    float* sPart = (float*)(smem + SPART_OFF);   // 4 x 128

    const int tid    = threadIdx.x;
    const int lane   = tid & 31;
    const int wid    = tid >> 5;                 // 0..7
    const int warp_m = wid >> 2;                 // 0..1 (tid<128 <=> warp_m 0)
    const int warp_n = wid & 3;                  // 0..3
    const int qid    = lane >> 2;
    const int tig    = lane & 3;
    const long long tile0 = (long long)blockIdx.x * TILE_M;

    const unsigned smem_u = (unsigned)__cvta_generic_to_shared(smem);
    const unsigned sA_u   = smem_u + SA_OFF;
    const unsigned sB0_u  = smem_u + SB0_OFF;
    const unsigned sB1_u  = smem_u + SB1_OFF;

    // ---- edge indices + small params ----
    {
        int half = (tid < 128) ? 0 : 1;
        int r = tid & 127;
        long long e = tile0 + r;
        int idx = 0;
        if (e < E) idx = ei[(long long)half * E + e];
        if (idx < 0)  idx = 0;
        if (idx >= N) idx = N - 1;
        sIdx[half * 128 + r] = idx;
    }
    if (tid < 128) {
        sW4[tid]         = W4[tid];
        sBias[tid]       = b1[tid];
        sBias[128 + tid] = b2[tid];
        sBias[256 + tid] = b3[tid];
    }
    __syncthreads();

    // ---- async loaders: 16 lanes per 256B row, 2 rows per warp-iter ----
    const int halfw = lane >> 4;       // 0/1
    const int l16   = lane & 15;
    auto load_act = [&](const int* idxs) {
        #pragma unroll
        for (int r = 0; r < 8; ++r) {
            int row = wid * 2 + halfw + r * 16;
            int node = idxs[row];
            cp16(sA_u + row * ROWB + l16 * 16,
                 (const char*)(g_xbf + (size_t)node * 128) + l16 * 16);
        }
    };
    auto load_w = [&](const __nv_bfloat16* W, unsigned dst_u) {
        #pragma unroll
        for (int r = 0; r < 8; ++r) {
            int row = wid * 2 + halfw + r * 16;
            cp16(dst_u + row * ROWB + l16 * 16,
                 (const char*)(W + row * 128) + l16 * 16);
        }
    };

    // ---- LDSM bases ----
    const int sub = lane >> 3;
    const int r8  = lane & 7;
    const unsigned aBase  = sA_u + (((sub & 1) * 8 + r8) * SAB + (sub >> 1) * 8) * 2;
    const unsigned bLocal = (unsigned)((((sub & 1) * 8 + r8) * SAB + warp_n * 32 + (sub >> 1) * 8) * 2);

    float acc[4][4][4];
    auto zero_acc = [&]() {
        #pragma unroll
        for (int mt = 0; mt < 4; ++mt)
            #pragma unroll
            for (int nt = 0; nt < 4; ++nt)
                #pragma unroll
                for (int i = 0; i < 4; ++i) acc[mt][nt][i] = 0.f;
    };

    auto run_mma = [&](unsigned sBu) {
        const unsigned bBase = sBu + bLocal;
        #pragma unroll
        for (int kt = 0; kt < 8; ++kt) {
            unsigned a[4][4], b[2][4];
            #pragma unroll
            for (int mt = 0; mt < 4; ++mt)
                ldsm_x4(a[mt], aBase + (unsigned)((warp_m * 64 + mt * 16) * SAB + kt * 16) * 2);
            #pragma unroll
            for (int ntp = 0; ntp < 2; ++ntp)
                ldsm_x4_t(b[ntp], bBase + (unsigned)(kt * 16 * SAB + ntp * 16) * 2);
            #pragma unroll
            for (int mt = 0; mt < 4; ++mt)
                #pragma unroll
                for (int nt = 0; nt < 4; ++nt)
                    mma_bf16(acc[mt][nt], a[mt], &b[nt >> 1][(nt & 1) * 2]);
        }
    };

    auto epilogue = [&](const float* __restrict__ bias) {
        #pragma unroll
        for (int mt = 0; mt < 4; ++mt) {
            int row = warp_m * 64 + mt * 16 + qid;
            #pragma unroll
            for (int nt = 0; nt < 4; ++nt) {
                int col = warp_n * 32 + nt * 8 + 2 * tig;
                float bb0 = bias[col];
                float bb1 = bias[col + 1];
                float v0 = fmaxf(acc[mt][nt][0] + bb0, 0.f);
                float v1 = fmaxf(acc[mt][nt][1] + bb1, 0.f);
                float v2 = fmaxf(acc[mt][nt][2] + bb0, 0.f);
                float v3 = fmaxf(acc[mt][nt][3] + bb1, 0.f);
                *(__nv_bfloat162*)(sA + row * SAB + col)       = __floats2bfloat162_rn(v0, v1);
                *(__nv_bfloat162*)(sA + (row + 8) * SAB + col) = __floats2bfloat162_rn(v2, v3);
            }
        }
    };

    // ======== pipeline ========
    load_act(sIdx);                      // g0: x_i -> sA, W1a -> sB0
    load_w(g_wbf + W1_OFF, sB0_u);
    CP_COMMIT();
    load_w(g_wbf + W1_OFF + 128 * 128, sB1_u);   // g1: W1b -> sB1
    CP_COMMIT();

    CP_WAIT(1);                          // g0 done (W1b streams under L1A)
    __syncthreads();
    zero_acc();
    run_mma(sB0_u);                      // L1A
    __syncthreads();                     // sA free (x_j rewrites all rows)

    load_act(sIdx + 128);                // g2: x_j -> sA
    CP_COMMIT();
    load_w(g_wbf + W2_OFF, sB0_u);       // g3: W2 -> sB0 (overlaps L1B)
    CP_COMMIT();

    CP_WAIT(1);                          // g1, g2 done
    __syncthreads();
    run_mma(sB1_u);                      // L1B (accumulate)
    CP_WAIT(0);                          // g3 (W2) done, per-thread
    __syncthreads();                     // full: sB1 free + W2 visible CTA-wide

    load_w(g_wbf + W3_OFF, sB1_u);       // g4: W3 -> sB1 (overlaps L2)
    CP_COMMIT();
    epilogue(sBias);                     // h1 -> sA (own warp_m half only)
    HALF_BAR(1 + warp_m);                // half-CTA dep: epilogue -> L2 A-reads
    zero_acc();
    run_mma(sB0_u);                      // L2
    CP_WAIT(0);                          // g4 (W3) done, per-thread
    __syncthreads();                     // full: W3 visible CTA-wide + sA reads done

    epilogue(sBias + 128);               // h2 -> sA (own half)
    HALF_BAR(1 + warp_m);
    zero_acc();
    run_mma(sB1_u);                      // L3

    // ======== L4 from registers: relu(acc + b3) . W4, quad-reduce ========
    #pragma unroll
    for (int mt = 0; mt < 4; ++mt) {
        float z0 = 0.f, z1 = 0.f;
        #pragma unroll
        for (int nt = 0; nt < 4; ++nt) {
            int col = warp_n * 32 + nt * 8 + 2 * tig;
            float bb0 = sBias[256 + col], bb1 = sBias[256 + col + 1];
            float w0  = sW4[col],         w1  = sW4[col + 1];
            z0 += fmaxf(acc[mt][nt][0] + bb0, 0.f) * w0
                + fmaxf(acc[mt][nt][1] + bb1, 0.f) * w1;
            z1 += fmaxf(acc[mt][nt][2] + bb0, 0.f) * w0
                + fmaxf(acc[mt][nt][3] + bb1, 0.f) * w1;
        }
        z0 += __shfl_xor_sync(0xFFFFFFFF, z0, 1);
        z0 += __shfl_xor_sync(0xFFFFFFFF, z0, 2);
        z1 += __shfl_xor_sync(0xFFFFFFFF, z1, 1);
        z1 += __shfl_xor_sync(0xFFFFFFFF, z1, 2);
        if (tig == 0) {
            int row = warp_m * 64 + mt * 16 + qid;
            sPart[warp_n * 128 + row]     = z0;
            sPart[warp_n * 128 + row + 8] = z1;
        }
    }
    __syncthreads();
    if (tid < 128) {
        long long e = tile0 + tid;
        if (e < E) {
            float z = sPart[tid] + sPart[128 + tid] + sPart[256 + tid]
                    + sPart[384 + tid] + __ldg(b4);
            out[e] = 1.f / (1.f + expf(-z));
        }
    }
}

extern "C" void kernel_launch(void* const* d_in, const int* in_sizes, int n_in,
                              void* d_out, int out_size)
{
    const float* x  = (const float*)d_in[0];
    const int*   ei = (const int*)d_in[1];
    const float* W1 = (const float*)d_in[2];
    const float* b1 = (const float*)d_in[3];
    const float* W2 = (const float*)d_in[4];
    const float* b2 = (const float*)d_in[5];
    const float* W3 = (const float*)d_in[6];
    const float* b3 = (const float*)d_in[7];
    const float* W4 = (const float*)d_in[8];
    const float* b4 = (const float*)d_in[9];
    float* out = (float*)d_out;

    int E = in_sizes[1] / 2;
    int N = in_sizes[0] / 128;
    if (N > MAX_N) N = MAX_N;

    int n8 = N * 16;
    cvt_x_kernel<<<(n8 + 511) / 512, 512>>>(x, n8);
    cvt_w_kernel<<<(W_TOTAL / 8 + 255) / 256, 256>>>(W1, W2, W3);

    int nTiles = (E + TILE_M - 1) / TILE_M;
    cudaFuncSetAttribute(edgepred_bf16_kernel,
                         cudaFuncAttributeMaxDynamicSharedMemorySize, SMEM_BYTES);
    edgepred_bf16_kernel<<<nTiles, THREADS, SMEM_BYTES>>>(
        ei, b1, b2, b3, W4, b4, out, E, N);
}